// round 10
// baseline (speedup 1.0000x reference)
#include <cuda_runtime.h>
#include <cuda_bf16.h>
#include <mma.h>
#include <math.h>
#include <stdint.h>

using namespace nvcuda;

#define NN 50000
#define NE 1000000
#define HIDD 64
#define SCAN_B 196   // ceil(NN/256)
#define LOG2E 1.4426950408889634f

// ---------------- scratch (device globals; no allocation allowed) ----------------
__device__ float         g_h[NN * HIDD];
__device__ float         g_zs[NN * HIDD];    // features pre-scaled by t[layer]*log2e
__device__ float         g_u[NN * HIDD];     // conv output (agg + z)
__device__ int           g_rowptr[NN + 1];
__device__ int           g_cnt[NN];
__device__ int           g_cursor[NN];
__device__ int           g_desc[SCAN_B];
__device__ uint2         g_edge[NE];         // {src, ea_bits}
__device__ float         g_psum[HIDD];
__device__ unsigned      g_pmax[HIDD];
__device__ __nv_bfloat16 g_w1h[3 * 8192];    // W1 bf16 split (hi/lo), [layer][64][128]
__device__ __nv_bfloat16 g_w1l[3 * 8192];
__device__ __nv_bfloat16 g_w2h[3 * 8192];    // W2, [layer][128][64]
__device__ __nv_bfloat16 g_w2l[3 * 8192];

__device__ __forceinline__ float ex2f(float x) {
    float r;
    asm("ex2.approx.f32 %0, %1;" : "=f"(r) : "f"(x));
    return r;
}

// ---------------- CSR histogram (vectorized dst reads) ----------------
__global__ void k_hist(const int* __restrict__ dst) {
    int i4 = blockIdx.x * blockDim.x + threadIdx.x;
    for (int i = i4; i < NE / 4; i += gridDim.x * blockDim.x) {
        int4 d = __ldg((const int4*)dst + i);
        atomicAdd(&g_cnt[d.x], 1);
        atomicAdd(&g_cnt[d.y], 1);
        atomicAdd(&g_cnt[d.z], 1);
        atomicAdd(&g_cnt[d.w], 1);
    }
}

// ---------------- single-pass scan (decoupled lookback), resets g_cnt/psum/pmax ----------------
__global__ void __launch_bounds__(256) k_scan() {
    int b = blockIdx.x;
    int t = threadIdx.x;
    int i = b * 256 + t;
    int lane = t & 31, w = t >> 5;
    int v = (i < NN) ? g_cnt[i] : 0;
    int x = v;
#pragma unroll
    for (int o = 1; o < 32; o <<= 1) {
        int y = __shfl_up_sync(0xffffffffu, x, o);
        if (lane >= o) x += y;
    }
    __shared__ int ws[8];
    __shared__ int sbase;
    if (lane == 31) ws[w] = x;
    __syncthreads();
    if (t < 8) {
        int y = ws[t];
#pragma unroll
        for (int o = 1; o < 8; o <<= 1) {
            int z = __shfl_up_sync(0x000000ffu, y, o);
            if (t >= o) y += z;
        }
        ws[t] = y;
    }
    __syncthreads();
    int wbase = w ? ws[w - 1] : 0;
    int incl = wbase + x;
    int agg = ws[7];

    if (t == 0) {
        if (b == 0) {
            atomicExch(&g_desc[0], (agg << 2) | 2);
            sbase = 0;
        } else {
            atomicExch(&g_desc[b], (agg << 2) | 1);
            int run = 0;
            int idx = b - 1;
            while (true) {
                int d = atomicAdd(&g_desc[idx], 0);
                int st = d & 3;
                if (st == 0) continue;
                run += (d >> 2);
                if (st == 2) break;
                idx--;
            }
            atomicExch(&g_desc[b], ((agg + run) << 2) | 2);
            sbase = run;
        }
    }
    __syncthreads();
    int excl = sbase + incl - v;
    if (i < NN) {
        g_rowptr[i] = excl;
        g_cursor[i] = excl;
        g_cnt[i] = 0;
    }
    if (b == 0 && t < HIDD) { g_psum[t] = 0.f; g_pmax[t] = 0u; }
    if (b == SCAN_B - 1 && t == 255) g_rowptr[NN] = NE;
}

// ------- scatter (packed edges) + node embedding + weight bf16-split prep, fused -------
#define SCAT_BLKS 1024
#define EMB_BLKS ((NN + 7) / 8)
#define WCV_BLKS 96   // 2*3*8192 / 512... (24576 W1 + 24576 W2 elems) / 256 = 192 thr-blocks of work in strided loop over 96 blocks
__global__ void __launch_bounds__(256) k_scatter_embed(const int* __restrict__ src,
                                                       const int* __restrict__ dst,
                                                       const float* __restrict__ ea,
                                                       const float* __restrict__ x,
                                                       const float* __restrict__ Wn,
                                                       const float* __restrict__ bn,
                                                       const float* __restrict__ t,
                                                       const float* __restrict__ W1,
                                                       const float* __restrict__ W2) {
    int blk = blockIdx.x;
    if (blk < SCAT_BLKS) {
        if (blk == 0 && threadIdx.x < SCAN_B) g_desc[threadIdx.x] = 0;
        for (int i = blk * 256 + threadIdx.x; i < NE; i += SCAT_BLKS * 256) {
            int d = dst[i];
            int s = src[i];
            float a = ea[i];
            int p = atomicAdd(&g_cursor[d], 1);
            g_edge[p] = make_uint2((unsigned)s, (unsigned)__float_as_int(a));
        }
    } else if (blk < SCAT_BLKS + EMB_BLKS) {
        int n = ((blk - SCAT_BLKS) * 256 + threadIdx.x) >> 5;
        if (n >= NN) return;
        int lane = threadIdx.x & 31;
        int c0 = lane * 2;
        float tc0 = __ldg(t) * LOG2E;
        float a0 = __ldg(bn + c0), a1 = __ldg(bn + c0 + 1);
        const float* xr = x + n * 16;
#pragma unroll
        for (int k = 0; k < 16; k++) {
            float xv = __ldg(xr + k);
            a0 = fmaf(xv, __ldg(Wn + k * HIDD + c0), a0);
            a1 = fmaf(xv, __ldg(Wn + k * HIDD + c0 + 1), a1);
        }
        g_h[n * HIDD + c0] = a0;
        g_h[n * HIDD + c0 + 1] = a1;
        float2 hs;
        hs.x = a0 * tc0;
        hs.y = a1 * tc0;
        *(float2*)(g_zs + n * HIDD + c0) = hs;
    } else {
        // weight bf16 hi/lo split: 24576 elems each for W1, W2
        int base = (blk - SCAT_BLKS - EMB_BLKS) * 256 + threadIdx.x;
        for (int i = base; i < 24576; i += WCV_BLKS * 256) {
            float v = __ldg(W1 + i);
            __nv_bfloat16 h = __float2bfloat16(v);
            g_w1h[i] = h;
            g_w1l[i] = __float2bfloat16(v - __bfloat162float(h));
            float v2 = __ldg(W2 + i);
            __nv_bfloat16 h2 = __float2bfloat16(v2);
            g_w2h[i] = h2;
            g_w2l[i] = __float2bfloat16(v2 - __bfloat162float(h2));
        }
    }
}

// ---------------- edge conv: warp per node, strength-reduced softmax (unchanged, validated) ----------------
__global__ void __launch_bounds__(256) k_conv(const float* __restrict__ W_edge,
                                              const float* __restrict__ b_edge,
                                              const float* __restrict__ t,
                                              int layer) {
    int n = (blockIdx.x * blockDim.x + threadIdx.x) >> 5;
    if (n >= NN) return;
    int lane = threadIdx.x & 31;
    int c0 = lane * 2;
    float tc = __ldg(t + layer) * LOG2E;
    float invtc = __fdividef(1.f, tc);
    float cc = 1e-7f * tc;
    float k1 = ex2f(cc);
    float k2 = k1 * tc;
    float k3 = tc * 1e-16f;
    float2 wev = *(const float2*)(W_edge + c0);
    float2 bev = *(const float2*)(b_edge + c0);
    float wet0 = wev.x * tc, wet1 = wev.y * tc;
    float bet0 = bev.x * tc, bet1 = bev.y * tc;
    int beg = g_rowptr[n], end = g_rowptr[n + 1];
    float s0 = 0.f, s1 = 0.f, w0 = 0.f, w1 = 0.f;
    int e = beg;
    for (; e + 2 <= end; e += 2) {
        uint2 pa = __ldg(&g_edge[e]);
        uint2 pb = __ldg(&g_edge[e + 1]);
        float aa = __int_as_float((int)pa.y);
        float ab = __int_as_float((int)pb.y);
        float2 xa = *(const float2*)(g_zs + pa.x * HIDD + c0);
        float2 xb = *(const float2*)(g_zs + pb.x * HIDD + c0);
        float ra0 = fmaxf(xa.x + fmaf(aa, wet0, bet0), 0.f);
        float ra1 = fmaxf(xa.y + fmaf(aa, wet1, bet1), 0.f);
        float rb0 = fmaxf(xb.x + fmaf(ab, wet0, bet0), 0.f);
        float rb1 = fmaxf(xb.y + fmaf(ab, wet1, bet1), 0.f);
        float ea0 = ex2f(ra0), ea1 = ex2f(ra1);
        float eb0 = ex2f(rb0), eb1 = ex2f(rb1);
        s0 += ea0 + eb0;
        s1 += ea1 + eb1;
        w0 = fmaf(ea0, ra0, fmaf(eb0, rb0, w0));
        w1 = fmaf(ea1, ra1, fmaf(eb1, rb1, w1));
    }
    if (e < end) {
        uint2 pa = __ldg(&g_edge[e]);
        float aa = __int_as_float((int)pa.y);
        float2 xa = *(const float2*)(g_zs + pa.x * HIDD + c0);
        float ra0 = fmaxf(xa.x + fmaf(aa, wet0, bet0), 0.f);
        float ra1 = fmaxf(xa.y + fmaf(aa, wet1, bet1), 0.f);
        float ea0 = ex2f(ra0), ea1 = ex2f(ra1);
        s0 += ea0;
        s1 += ea1;
        w0 = fmaf(ea0, ra0, w0);
        w1 = fmaf(ea1, ra1, w1);
    }
    float2 zsv = *(const float2*)(g_zs + n * HIDD + c0);
    float2 uo;
    uo.x = __fdividef(k1 * fmaf(cc, s0, w0), fmaf(k2, s0, k3)) + zsv.x * invtc;
    uo.y = __fdividef(k1 * fmaf(cc, s1, w1), fmaf(k2, s1, k3)) + zsv.y * invtc;
    *(float2*)(g_u + n * HIDD + c0) = uo;
}

// ---------------- tensor-core MLP via wmma (HMMA), bf16-x3 split ----------------
// 64 nodes/block, 256 threads (8 warps).
// GEMM1: D1[64,128] = U[64,64] @ W1[64,128]; GEMM2: D2[64,64] = Z[64,128] @ W2[128,64].
// smem byte offsets:
#define TM_UH   0        // 64x64 bf16 = 8192
#define TM_UL   8192
#define TM_W1H  16384    // 64x128 bf16 = 16384
#define TM_W1L  32768
#define TM_W2H  49152    // 128x64 bf16 = 16384
#define TM_W2L  65536
#define TM_ZF   81920    // 64x132 f32 = 33792
#define TM_ZH   0        // reuse UH+UL after GEMM1 (64x128 bf16 = 16384)
#define TM_ZL   16384    // reuse W1H after GEMM1
#define TM_C2   81920    // reuse ZF after epilogue1 (64x68 f32 = 17408)
#define TM_BIAS 115712
#define TMLP_SMEM (115712 + 2304)
#define TMLP_BLKS ((NN + 63) / 64)

__global__ void __launch_bounds__(256) k_tmlp(const float* __restrict__ b1,
                                              const float* __restrict__ g1,
                                              const float* __restrict__ be1,
                                              const float* __restrict__ b2,
                                              const float* __restrict__ norm_g,
                                              const float* __restrict__ norm_b,
                                              const float* __restrict__ t,
                                              int layer, int addRes, int ln_idx,
                                              int doPool) {
    extern __shared__ char smem[];
    int tid = threadIdx.x, warp = tid >> 5;
    int nodeBase = blockIdx.x * 64;

    __nv_bfloat16* uh = (__nv_bfloat16*)(smem + TM_UH);
    __nv_bfloat16* ul = (__nv_bfloat16*)(smem + TM_UL);
    __nv_bfloat16* w1h = (__nv_bfloat16*)(smem + TM_W1H);
    __nv_bfloat16* w1l = (__nv_bfloat16*)(smem + TM_W1L);
    __nv_bfloat16* w2h = (__nv_bfloat16*)(smem + TM_W2H);
    __nv_bfloat16* w2l = (__nv_bfloat16*)(smem + TM_W2L);
    float* zf = (float*)(smem + TM_ZF);
    float* sb1 = (float*)(smem + TM_BIAS);  // 128
    float* sg1 = sb1 + 128;                  // 128
    float* sbe = sg1 + 128;                  // 128
    float* sb2 = sbe + 128;                  // 64
    float* sng = sb2 + 64;                   // 64
    float* snb = sng + 64;                   // 64

    // stage U (convert to bf16 hi/lo)
    for (int i = tid; i < 4096; i += 256) {
        int r = i >> 6, c = i & 63;
        int n = nodeBase + r;
        float v = (n < NN) ? __ldg(g_u + (size_t)n * 64 + c) : 0.f;
        __nv_bfloat16 h = __float2bfloat16(v);
        uh[i] = h;
        ul[i] = __float2bfloat16(v - __bfloat162float(h));
    }
    // stage pre-split weights (uint4 bulk)
    {
        const uint4* s1h = (const uint4*)(g_w1h + layer * 8192);
        const uint4* s1l = (const uint4*)(g_w1l + layer * 8192);
        const uint4* s2h = (const uint4*)(g_w2h + layer * 8192);
        const uint4* s2l = (const uint4*)(g_w2l + layer * 8192);
        uint4* d1h = (uint4*)w1h;
        uint4* d1l = (uint4*)w1l;
        uint4* d2h = (uint4*)w2h;
        uint4* d2l = (uint4*)w2l;
        for (int i = tid; i < 1024; i += 256) {
            d1h[i] = __ldg(s1h + i);
            d1l[i] = __ldg(s1l + i);
            d2h[i] = __ldg(s2h + i);
            d2l[i] = __ldg(s2l + i);
        }
    }
    if (tid < 128) {
        sb1[tid] = __ldg(b1 + layer * 128 + tid);
        sg1[tid] = __ldg(g1 + layer * 128 + tid);
        sbe[tid] = __ldg(be1 + layer * 128 + tid);
    }
    if (tid < 64) {
        sb2[tid] = __ldg(b2 + layer * 64 + tid);
        sng[tid] = __ldg(norm_g + ln_idx * HIDD + tid);
        snb[tid] = __ldg(norm_b + ln_idx * HIDD + tid);
    }
    __syncthreads();

    // ---- GEMM1: warp -> row-tile rt=warp>>1 (16 rows), col-half ch=(warp&1)*64 (4 col tiles)
    {
        int rt = warp >> 1;
        int chf = (warp & 1) * 64;
        wmma::fragment<wmma::accumulator, 16, 16, 16, float> acc[4];
#pragma unroll
        for (int ct = 0; ct < 4; ct++) wmma::fill_fragment(acc[ct], 0.f);
        wmma::fragment<wmma::matrix_a, 16, 16, 16, __nv_bfloat16, wmma::row_major> fa;
        wmma::fragment<wmma::matrix_b, 16, 16, 16, __nv_bfloat16, wmma::row_major> fb;
#pragma unroll
        for (int p = 0; p < 3; p++) {
            const __nv_bfloat16* A = (p == 2) ? ul : uh;
            const __nv_bfloat16* B = (p == 1) ? w1l : w1h;
#pragma unroll
            for (int ks = 0; ks < 4; ks++) {
                wmma::load_matrix_sync(fa, A + rt * 16 * 64 + ks * 16, 64);
#pragma unroll
                for (int ct = 0; ct < 4; ct++) {
                    wmma::load_matrix_sync(fb, B + ks * 16 * 128 + chf + ct * 16, 128);
                    wmma::mma_sync(acc[ct], fa, fb, acc[ct]);
                }
            }
        }
#pragma unroll
        for (int ct = 0; ct < 4; ct++)
            wmma::store_matrix_sync(zf + rt * 16 * 132 + chf + ct * 16, acc[ct], 132,
                                    wmma::mem_row_major);
    }
    __syncthreads();

    // ---- epilogue1: +b1, LN(128), relu -> Zh/Zl bf16 (thread t<64 owns row t)
    __nv_bfloat16* zh = (__nv_bfloat16*)(smem + TM_ZH);
    __nv_bfloat16* zl = (__nv_bfloat16*)(smem + TM_ZL);
    if (tid < 64) {
        float* row = zf + tid * 132;
        float sum = 0.f, sq = 0.f;
#pragma unroll 8
        for (int c = 0; c < 128; c++) {
            float v = row[c] + sb1[c];
            row[c] = v;
            sum += v;
            sq = fmaf(v, v, sq);
        }
        float mu = sum * (1.f / 128.f);
        float var = sq * (1.f / 128.f) - mu * mu;
        float rs = rsqrtf(var + 1e-5f);
#pragma unroll 8
        for (int c = 0; c < 128; c++) {
            float z = fmaxf(fmaf((row[c] - mu) * rs, sg1[c], sbe[c]), 0.f);
            __nv_bfloat16 h = __float2bfloat16(z);
            zh[tid * 128 + c] = h;
            zl[tid * 128 + c] = __float2bfloat16(z - __bfloat162float(h));
        }
    }
    __syncthreads();

    // ---- GEMM2: warp -> row-tile rt=warp>>1, col base (warp&1)*32 (2 col tiles)
    float* c2 = (float*)(smem + TM_C2);
    {
        int rt = warp >> 1;
        int cb = (warp & 1) * 32;
        wmma::fragment<wmma::accumulator, 16, 16, 16, float> acc[2];
        wmma::fill_fragment(acc[0], 0.f);
        wmma::fill_fragment(acc[1], 0.f);
        wmma::fragment<wmma::matrix_a, 16, 16, 16, __nv_bfloat16, wmma::row_major> fa;
        wmma::fragment<wmma::matrix_b, 16, 16, 16, __nv_bfloat16, wmma::row_major> fb;
#pragma unroll
        for (int p = 0; p < 3; p++) {
            const __nv_bfloat16* A = (p == 2) ? zl : zh;
            const __nv_bfloat16* B = (p == 1) ? w2l : w2h;
#pragma unroll
            for (int ks = 0; ks < 8; ks++) {
                wmma::load_matrix_sync(fa, A + rt * 16 * 128 + ks * 16, 128);
#pragma unroll
                for (int ct = 0; ct < 2; ct++) {
                    wmma::load_matrix_sync(fb, B + ks * 16 * 64 + cb + ct * 16, 64);
                    wmma::mma_sync(acc[ct], fa, fb, acc[ct]);
                }
            }
        }
        wmma::store_matrix_sync(c2 + rt * 16 * 68 + cb, acc[0], 68, wmma::mem_row_major);
        wmma::store_matrix_sync(c2 + rt * 16 * 68 + cb + 16, acc[1], 68, wmma::mem_row_major);
    }
    __syncthreads();

    // ---- epilogue2: +b2 (+res) -> h, LN(64) -> zs or pool (thread t<64 owns row t)
    if (tid < 64) {
        int n = nodeBase + tid;
        bool valid = n < NN;
        float* crow = c2 + tid * 68;
        float sum = 0.f, sq = 0.f;
        if (valid && addRes) {
            const float4* hp = (const float4*)(g_h + (size_t)n * 64);
#pragma unroll
            for (int j = 0; j < 16; j++) {
                float4 hv = __ldg(hp + j);
                float v0 = crow[4 * j] + sb2[4 * j] + hv.x;
                float v1 = crow[4 * j + 1] + sb2[4 * j + 1] + hv.y;
                float v2 = crow[4 * j + 2] + sb2[4 * j + 2] + hv.z;
                float v3 = crow[4 * j + 3] + sb2[4 * j + 3] + hv.w;
                crow[4 * j] = v0;
                crow[4 * j + 1] = v1;
                crow[4 * j + 2] = v2;
                crow[4 * j + 3] = v3;
                sum += v0 + v1 + v2 + v3;
                sq = fmaf(v0, v0, fmaf(v1, v1, fmaf(v2, v2, fmaf(v3, v3, sq))));
            }
        } else {
#pragma unroll 8
            for (int c = 0; c < 64; c++) {
                float v = crow[c] + sb2[c];
                crow[c] = v;
                sum += v;
                sq = fmaf(v, v, sq);
            }
        }
        if (valid && !doPool) {
            float4* hp = (float4*)(g_h + (size_t)n * 64);
#pragma unroll
            for (int j = 0; j < 16; j++)
                hp[j] = make_float4(crow[4 * j], crow[4 * j + 1], crow[4 * j + 2],
                                    crow[4 * j + 3]);
        }
        float mu = sum * (1.f / 64.f);
        float var = sq * (1.f / 64.f) - mu * mu;
        float rs = rsqrtf(var + 1e-5f);
        if (!doPool) {
            if (valid) {
                float zscale = __ldg(t + layer + 1) * LOG2E;
                float4* zp = (float4*)(g_zs + (size_t)n * 64);
#pragma unroll
                for (int j = 0; j < 16; j++) {
                    float z0 = fmaxf(fmaf((crow[4 * j] - mu) * rs, sng[4 * j], snb[4 * j]), 0.f);
                    float z1 = fmaxf(fmaf((crow[4 * j + 1] - mu) * rs, sng[4 * j + 1], snb[4 * j + 1]), 0.f);
                    float z2 = fmaxf(fmaf((crow[4 * j + 2] - mu) * rs, sng[4 * j + 2], snb[4 * j + 2]), 0.f);
                    float z3 = fmaxf(fmaf((crow[4 * j + 3] - mu) * rs, sng[4 * j + 3], snb[4 * j + 3]), 0.f);
                    zp[j] = make_float4(z0 * zscale, z1 * zscale, z2 * zscale, z3 * zscale);
                }
            }
        } else {
            // write LN'd z back to crow for column-wise pool reduce
#pragma unroll 8
            for (int c = 0; c < 64; c++)
                crow[c] = fmaxf(fmaf((crow[c] - mu) * rs, sng[c], snb[c]), 0.f);
        }
    }
    __syncthreads();
    if (doPool && tid < 64) {
        int cnt = NN - nodeBase;
        if (cnt > 64) cnt = 64;
        float s = 0.f, m = 0.f;
        for (int j = 0; j < cnt; j++) {
            float v = c2[j * 68 + tid];
            s += v;
            m = fmaxf(m, v);
        }
        atomicAdd(&g_psum[tid], s);
        atomicMax(&g_pmax[tid], __float_as_uint(m));
    }
}

// ---------------- head: pair-pool to emb[64], emb @ W_lin + b_lin ----------------
__global__ void __launch_bounds__(64) k_head(const float* __restrict__ W_lin,
                                             const float* __restrict__ b_lin,
                                             float* __restrict__ out) {
    __shared__ float emb[64];
    int t = threadIdx.x;
    if (t < 32) {
        emb[t] = (g_psum[2 * t] + g_psum[2 * t + 1]) * (1.f / (2.f * (float)NN));
        emb[32 + t] = fmaxf(__uint_as_float(g_pmax[2 * t]), __uint_as_float(g_pmax[2 * t + 1]));
    }
    __syncthreads();
    float acc = __ldg(b_lin + t);
#pragma unroll 8
    for (int k = 0; k < 64; k++) acc = fmaf(emb[k], __ldg(W_lin + k * 64 + t), acc);
    out[t] = acc;
}

// ---------------- launch ----------------
extern "C" void kernel_launch(void* const* d_in, const int* in_sizes, int n_in,
                              void* d_out, int out_size) {
    const float* x = (const float*)d_in[0];
    const float* edge_attr = (const float*)d_in[1];
    const int* eidx = (const int*)d_in[2];
    const float* W_node = (const float*)d_in[3];
    const float* b_node = (const float*)d_in[4];
    const float* W_edge = (const float*)d_in[5];
    const float* b_edge = (const float*)d_in[6];
    const float* t = (const float*)d_in[7];
    const float* W1 = (const float*)d_in[8];
    const float* b1 = (const float*)d_in[9];
    const float* ln_g = (const float*)d_in[10];
    const float* ln_b = (const float*)d_in[11];
    const float* W2 = (const float*)d_in[12];
    const float* b2 = (const float*)d_in[13];
    const float* norm_g = (const float*)d_in[14];
    const float* norm_b = (const float*)d_in[15];
    const float* W_lin = (const float*)d_in[16];
    const float* b_lin = (const float*)d_in[17];
    float* out = (float*)d_out;

    const int* src = eidx;
    const int* dst = eidx + NE;

    cudaFuncSetAttribute(k_tmlp, cudaFuncAttributeMaxDynamicSharedMemorySize, TMLP_SMEM);

    const int WARP_BLKS = (NN * 32 + 255) / 256;  // warp-per-node conv

    k_hist<<<512, 256>>>(dst);
    k_scan<<<SCAN_B, 256>>>();
    k_scatter_embed<<<SCAT_BLKS + EMB_BLKS + WCV_BLKS, 256>>>(src, dst, edge_attr, x,
                                                              W_node, b_node, t, W1, W2);

    // layer 0 (conv = launch #4, profiled)
    k_conv<<<WARP_BLKS, 256>>>(W_edge, b_edge, t, 0);
    k_tmlp<<<TMLP_BLKS, 256, TMLP_SMEM>>>(b1, ln_g, ln_b, b2, norm_g, norm_b, t, 0, 0, 1, 0);
    // layer 1
    k_conv<<<WARP_BLKS, 256>>>(W_edge, b_edge, t, 1);
    k_tmlp<<<TMLP_BLKS, 256, TMLP_SMEM>>>(b1, ln_g, ln_b, b2, norm_g, norm_b, t, 1, 1, 2, 0);
    // layer 2 (pool fused; final norm uses layer-0 params)
    k_conv<<<WARP_BLKS, 256>>>(W_edge, b_edge, t, 2);
    k_tmlp<<<TMLP_BLKS, 256, TMLP_SMEM>>>(b1, ln_g, ln_b, b2, norm_g, norm_b, t, 2, 1, 0, 1);

    k_head<<<1, 64>>>(W_lin, b_lin, out);
}

// round 11
// speedup vs baseline: 2.2129x; 2.2129x over previous
#include <cuda_runtime.h>
#include <math.h>
#include <stdint.h>

#define NN 50000
#define NE 1000000
#define HIDD 64
#define SCAN_B 196   // ceil(NN/256)
#define LOG2E 1.4426950408889634f

// ---------------- scratch (device globals; no allocation allowed) ----------------
__device__ float    g_h[NN * HIDD];     // accumulator stream (residuals)
__device__ float    g_zs[NN * HIDD];    // features pre-scaled by t[layer]*log2e
__device__ float    g_u[NN * HIDD];     // conv output (agg + z)
__device__ int      g_rowptr[NN + 1];
__device__ int      g_cnt[NN];
__device__ int      g_cursor[NN];
__device__ int      g_desc[SCAN_B];
__device__ uint2    g_edge[NE];         // {src, ea_bits}
__device__ float    g_psum[HIDD];
__device__ unsigned g_pmax[HIDD];

__device__ __forceinline__ float ex2f(float x) {
    float r;
    asm("ex2.approx.f32 %0, %1;" : "=f"(r) : "f"(x));
    return r;
}

// ---------------- CSR histogram (vectorized dst reads) ----------------
__global__ void k_hist(const int* __restrict__ dst) {
    int i4 = blockIdx.x * blockDim.x + threadIdx.x;
    for (int i = i4; i < NE / 4; i += gridDim.x * blockDim.x) {
        int4 d = __ldg((const int4*)dst + i);
        atomicAdd(&g_cnt[d.x], 1);
        atomicAdd(&g_cnt[d.y], 1);
        atomicAdd(&g_cnt[d.z], 1);
        atomicAdd(&g_cnt[d.w], 1);
    }
}

// ---------------- single-pass scan (decoupled lookback), resets g_cnt/psum/pmax ----------------
__global__ void __launch_bounds__(256) k_scan() {
    int b = blockIdx.x;
    int t = threadIdx.x;
    int i = b * 256 + t;
    int lane = t & 31, w = t >> 5;
    int v = (i < NN) ? g_cnt[i] : 0;
    int x = v;
#pragma unroll
    for (int o = 1; o < 32; o <<= 1) {
        int y = __shfl_up_sync(0xffffffffu, x, o);
        if (lane >= o) x += y;
    }
    __shared__ int ws[8];
    __shared__ int sbase;
    if (lane == 31) ws[w] = x;
    __syncthreads();
    if (t < 8) {
        int y = ws[t];
#pragma unroll
        for (int o = 1; o < 8; o <<= 1) {
            int z = __shfl_up_sync(0x000000ffu, y, o);
            if (t >= o) y += z;
        }
        ws[t] = y;
    }
    __syncthreads();
    int wbase = w ? ws[w - 1] : 0;
    int incl = wbase + x;
    int agg = ws[7];

    if (t == 0) {
        if (b == 0) {
            atomicExch(&g_desc[0], (agg << 2) | 2);
            sbase = 0;
        } else {
            atomicExch(&g_desc[b], (agg << 2) | 1);
            int run = 0;
            int idx = b - 1;
            while (true) {
                int d = atomicAdd(&g_desc[idx], 0);
                int st = d & 3;
                if (st == 0) continue;
                run += (d >> 2);
                if (st == 2) break;
                idx--;
            }
            atomicExch(&g_desc[b], ((agg + run) << 2) | 2);
            sbase = run;
        }
    }
    __syncthreads();
    int excl = sbase + incl - v;
    if (i < NN) {
        g_rowptr[i] = excl;
        g_cursor[i] = excl;
        g_cnt[i] = 0;
    }
    if (b == 0 && t < HIDD) { g_psum[t] = 0.f; g_pmax[t] = 0u; }
    if (b == SCAN_B - 1 && t == 255) g_rowptr[NN] = NE;
}

// ---------------- scatter (2 edges/thread, packed records) + node embedding ----------------
#define SCAT_BLKS 1024
#define EMB_BLKS ((NN + 7) / 8)
__global__ void __launch_bounds__(256) k_scatter_embed(const int* __restrict__ src,
                                                       const int* __restrict__ dst,
                                                       const float* __restrict__ ea,
                                                       const float* __restrict__ x,
                                                       const float* __restrict__ Wn,
                                                       const float* __restrict__ bn,
                                                       const float* __restrict__ t) {
    int blk = blockIdx.x;
    if (blk < SCAT_BLKS) {
        if (blk == 0 && threadIdx.x < SCAN_B) g_desc[threadIdx.x] = 0;
        int g = blk * 256 + threadIdx.x;
        for (int i = g; i < NE / 2; i += SCAT_BLKS * 256) {
            int2 s2 = __ldg((const int2*)src + i);
            int2 d2 = __ldg((const int2*)dst + i);
            float2 a2 = __ldg((const float2*)ea + i);
            int p0 = atomicAdd(&g_cursor[d2.x], 1);
            g_edge[p0] = make_uint2((unsigned)s2.x, (unsigned)__float_as_int(a2.x));
            int p1 = atomicAdd(&g_cursor[d2.y], 1);
            g_edge[p1] = make_uint2((unsigned)s2.y, (unsigned)__float_as_int(a2.y));
        }
    } else {
        int n = ((blk - SCAT_BLKS) * 256 + threadIdx.x) >> 5;
        if (n >= NN) return;
        int lane = threadIdx.x & 31;
        int c0 = lane * 2;
        float tc0 = __ldg(t) * LOG2E;
        float a0 = __ldg(bn + c0), a1 = __ldg(bn + c0 + 1);
        const float* xr = x + n * 16;
#pragma unroll
        for (int k = 0; k < 16; k++) {
            float xv = __ldg(xr + k);
            a0 = fmaf(xv, __ldg(Wn + k * HIDD + c0), a0);
            a1 = fmaf(xv, __ldg(Wn + k * HIDD + c0 + 1), a1);
        }
        g_h[n * HIDD + c0] = a0;
        g_h[n * HIDD + c0 + 1] = a1;
        float2 hs;
        hs.x = a0 * tc0;
        hs.y = a1 * tc0;
        *(float2*)(g_zs + n * HIDD + c0) = hs;
    }
}

// ---------------- edge conv: warp per node, strength-reduced softmax ----------------
// LDG.128 paired edge loads (alignment prologue), unroll-4 gather pipeline.
__global__ void __launch_bounds__(256) k_conv(const float* __restrict__ W_edge,
                                              const float* __restrict__ b_edge,
                                              const float* __restrict__ t,
                                              int layer) {
    int n = (blockIdx.x * blockDim.x + threadIdx.x) >> 5;
    if (n >= NN) return;
    int lane = threadIdx.x & 31;
    int c0 = lane * 2;
    float tc = __ldg(t + layer) * LOG2E;
    float invtc = __fdividef(1.f, tc);
    float cc = 1e-7f * tc;
    float k1 = ex2f(cc);
    float k2 = k1 * tc;
    float k3 = tc * 1e-16f;
    float2 wev = *(const float2*)(W_edge + c0);
    float2 bev = *(const float2*)(b_edge + c0);
    float wet0 = wev.x * tc, wet1 = wev.y * tc;
    float bet0 = bev.x * tc, bet1 = bev.y * tc;
    const float* zrow = g_zs + c0;
    int beg = g_rowptr[n], end = g_rowptr[n + 1];
    float s0 = 0.f, s1 = 0.f, w0 = 0.f, w1 = 0.f;

#define EDGE1(SP, AV) do {                                                   \
        float2 _x = *(const float2*)(zrow + (size_t)(SP) * HIDD);            \
        float _r0 = fmaxf(_x.x + fmaf((AV), wet0, bet0), 0.f);               \
        float _r1 = fmaxf(_x.y + fmaf((AV), wet1, bet1), 0.f);               \
        float _e0 = ex2f(_r0), _e1 = ex2f(_r1);                              \
        s0 += _e0;                                                           \
        s1 += _e1;                                                           \
        w0 = fmaf(_e0, _r0, w0);                                             \
        w1 = fmaf(_e1, _r1, w1);                                             \
    } while (0)

    int e = beg;
    if ((e & 1) && e < end) {  // align to even for 16B loads
        uint2 p = __ldg(&g_edge[e]);
        EDGE1(p.x, __int_as_float((int)p.y));
        e++;
    }
    for (; e + 4 <= end; e += 4) {
        uint4 qa = __ldg((const uint4*)(g_edge + e));       // edges e, e+1
        uint4 qb = __ldg((const uint4*)(g_edge + e + 2));   // edges e+2, e+3
        float a0e = __int_as_float((int)qa.y);
        float a1e = __int_as_float((int)qa.w);
        float a2e = __int_as_float((int)qb.y);
        float a3e = __int_as_float((int)qb.w);
        float2 x0 = *(const float2*)(zrow + (size_t)qa.x * HIDD);
        float2 x1 = *(const float2*)(zrow + (size_t)qa.z * HIDD);
        float2 x2 = *(const float2*)(zrow + (size_t)qb.x * HIDD);
        float2 x3 = *(const float2*)(zrow + (size_t)qb.z * HIDD);
        float r00 = fmaxf(x0.x + fmaf(a0e, wet0, bet0), 0.f);
        float r01 = fmaxf(x0.y + fmaf(a0e, wet1, bet1), 0.f);
        float r10 = fmaxf(x1.x + fmaf(a1e, wet0, bet0), 0.f);
        float r11 = fmaxf(x1.y + fmaf(a1e, wet1, bet1), 0.f);
        float r20 = fmaxf(x2.x + fmaf(a2e, wet0, bet0), 0.f);
        float r21 = fmaxf(x2.y + fmaf(a2e, wet1, bet1), 0.f);
        float r30 = fmaxf(x3.x + fmaf(a3e, wet0, bet0), 0.f);
        float r31 = fmaxf(x3.y + fmaf(a3e, wet1, bet1), 0.f);
        float e00 = ex2f(r00), e01 = ex2f(r01);
        float e10 = ex2f(r10), e11 = ex2f(r11);
        float e20 = ex2f(r20), e21 = ex2f(r21);
        float e30 = ex2f(r30), e31 = ex2f(r31);
        s0 += (e00 + e10) + (e20 + e30);
        s1 += (e01 + e11) + (e21 + e31);
        w0 = fmaf(e00, r00, fmaf(e10, r10, fmaf(e20, r20, fmaf(e30, r30, w0))));
        w1 = fmaf(e01, r01, fmaf(e11, r11, fmaf(e21, r21, fmaf(e31, r31, w1))));
    }
    if (e + 2 <= end) {
        uint4 qa = __ldg((const uint4*)(g_edge + e));
        float a0e = __int_as_float((int)qa.y);
        float a1e = __int_as_float((int)qa.w);
        float2 x0 = *(const float2*)(zrow + (size_t)qa.x * HIDD);
        float2 x1 = *(const float2*)(zrow + (size_t)qa.z * HIDD);
        float r00 = fmaxf(x0.x + fmaf(a0e, wet0, bet0), 0.f);
        float r01 = fmaxf(x0.y + fmaf(a0e, wet1, bet1), 0.f);
        float r10 = fmaxf(x1.x + fmaf(a1e, wet0, bet0), 0.f);
        float r11 = fmaxf(x1.y + fmaf(a1e, wet1, bet1), 0.f);
        float e00 = ex2f(r00), e01 = ex2f(r01);
        float e10 = ex2f(r10), e11 = ex2f(r11);
        s0 += e00 + e10;
        s1 += e01 + e11;
        w0 = fmaf(e00, r00, fmaf(e10, r10, w0));
        w1 = fmaf(e01, r01, fmaf(e11, r11, w1));
        e += 2;
    }
    if (e < end) {
        uint2 p = __ldg(&g_edge[e]);
        EDGE1(p.x, __int_as_float((int)p.y));
    }
#undef EDGE1

    float2 zsv = *(const float2*)(zrow + (size_t)n * HIDD);
    float2 uo;
    uo.x = __fdividef(k1 * fmaf(cc, s0, w0), fmaf(k2, s0, k3)) + zsv.x * invtc;
    uo.y = __fdividef(k1 * fmaf(cc, s1, w1), fmaf(k2, s1, k3)) + zsv.y * invtc;
    *(float2*)(g_u + n * HIDD + c0) = uo;
}

// ---------------- per-node MLP + fused output LN (+ pool / pre-scaled feature write) ----------------
__global__ void __launch_bounds__(256, 2) k_mlp(const float* __restrict__ W1,
                                                const float* __restrict__ b1,
                                                const float* __restrict__ g1,
                                                const float* __restrict__ be1,
                                                const float* __restrict__ W2,
                                                const float* __restrict__ b2,
                                                const float* __restrict__ norm_g,
                                                const float* __restrict__ norm_b,
                                                const float* __restrict__ t,
                                                int layer, int addRes, int ln_idx,
                                                int doPool) {
    extern __shared__ float sm[];
    float* sW1 = sm;            // 8192
    float* sW2 = sm + 8192;     // 8192
    float* sA = sm + 16384;     // 8192: U tile (64x64) then Z tile (64x128)
    float* sb1 = sm + 24576;    // 128
    float* sg1 = sb1 + 128;     // 128
    float* sbe = sg1 + 128;     // 128
    float* sb2 = sbe + 128;     // 64
    float* sPS = sb2 + 64;      // 64 pool sums
    unsigned* sPM = (unsigned*)(sPS + 64);  // 64 pool maxes
    int tid = threadIdx.x;
    const float* W1l = W1 + layer * 8192;
    const float* W2l = W2 + layer * 8192;
    for (int i = tid; i < 8192; i += 256) {
        sW1[i] = __ldg(W1l + i);
        sW2[i] = __ldg(W2l + i);
    }
    if (tid < 128) {
        sb1[tid] = __ldg(b1 + layer * 128 + tid);
        sg1[tid] = __ldg(g1 + layer * 128 + tid);
        sbe[tid] = __ldg(be1 + layer * 128 + tid);
    }
    if (tid < 64) {
        sb2[tid] = __ldg(b2 + layer * 64 + tid);
        sPS[tid] = 0.f;
        sPM[tid] = 0u;
    }
    int nodeBase = blockIdx.x * 64;
    for (int i = tid; i < 4096; i += 256) {
        int n = nodeBase + (i >> 6);
        sA[i] = (n < NN) ? g_u[n * HIDD + (i & 63)] : 0.f;
    }
    __syncthreads();

    int warp = tid >> 5, lane = tid & 31;
    int r0 = warp * 8;
    int cb = lane * 4;
    float acc[8][4];
#pragma unroll
    for (int j = 0; j < 8; j++) acc[j][0] = acc[j][1] = acc[j][2] = acc[j][3] = 0.f;
#pragma unroll
    for (int k4 = 0; k4 < 64; k4 += 4) {
        float4 wr0 = *(const float4*)&sW1[(k4 + 0) * 128 + cb];
        float4 wr1 = *(const float4*)&sW1[(k4 + 1) * 128 + cb];
        float4 wr2 = *(const float4*)&sW1[(k4 + 2) * 128 + cb];
        float4 wr3 = *(const float4*)&sW1[(k4 + 3) * 128 + cb];
#pragma unroll
        for (int j = 0; j < 8; j++) {
            float4 av = *(const float4*)&sA[(r0 + j) * 64 + k4];
            acc[j][0] = fmaf(av.x, wr0.x, acc[j][0]);
            acc[j][1] = fmaf(av.x, wr0.y, acc[j][1]);
            acc[j][2] = fmaf(av.x, wr0.z, acc[j][2]);
            acc[j][3] = fmaf(av.x, wr0.w, acc[j][3]);
            acc[j][0] = fmaf(av.y, wr1.x, acc[j][0]);
            acc[j][1] = fmaf(av.y, wr1.y, acc[j][1]);
            acc[j][2] = fmaf(av.y, wr1.z, acc[j][2]);
            acc[j][3] = fmaf(av.y, wr1.w, acc[j][3]);
            acc[j][0] = fmaf(av.z, wr2.x, acc[j][0]);
            acc[j][1] = fmaf(av.z, wr2.y, acc[j][1]);
            acc[j][2] = fmaf(av.z, wr2.z, acc[j][2]);
            acc[j][3] = fmaf(av.z, wr2.w, acc[j][3]);
            acc[j][0] = fmaf(av.w, wr3.x, acc[j][0]);
            acc[j][1] = fmaf(av.w, wr3.y, acc[j][1]);
            acc[j][2] = fmaf(av.w, wr3.z, acc[j][2]);
            acc[j][3] = fmaf(av.w, wr3.w, acc[j][3]);
        }
    }
    __syncthreads();
    float* sZ = sA;   // overlay 64x128
    float b1v[4], gb[4], bb[4];
#pragma unroll
    for (int q = 0; q < 4; q++) {
        b1v[q] = sb1[cb + q];
        gb[q] = sg1[cb + q];
        bb[q] = sbe[cb + q];
    }
#pragma unroll
    for (int j = 0; j < 8; j++) {
        float v[4];
        float sum = 0.f, sq = 0.f;
#pragma unroll
        for (int q = 0; q < 4; q++) {
            v[q] = acc[j][q] + b1v[q];
            sum += v[q];
            sq = fmaf(v[q], v[q], sq);
        }
#pragma unroll
        for (int o = 16; o; o >>= 1) {
            sum += __shfl_xor_sync(0xffffffffu, sum, o);
            sq += __shfl_xor_sync(0xffffffffu, sq, o);
        }
        float mu = sum * (1.f / 128.f);
        float var = sq * (1.f / 128.f) - mu * mu;
        float rs = rsqrtf(var + 1e-5f);
#pragma unroll
        for (int q = 0; q < 4; q++) {
            float z = fmaxf(fmaf((v[q] - mu) * rs, gb[q], bb[q]), 0.f);
            sZ[(r0 + j) * 128 + cb + q] = z;
        }
    }
    __syncthreads();
    int c2 = lane * 2;
    float a2[8][2];
#pragma unroll
    for (int j = 0; j < 8; j++) { a2[j][0] = 0.f; a2[j][1] = 0.f; }
#pragma unroll
    for (int k4 = 0; k4 < 128; k4 += 4) {
        float2 u0 = *(const float2*)&sW2[(k4 + 0) * 64 + c2];
        float2 u1 = *(const float2*)&sW2[(k4 + 1) * 64 + c2];
        float2 u2 = *(const float2*)&sW2[(k4 + 2) * 64 + c2];
        float2 u3 = *(const float2*)&sW2[(k4 + 3) * 64 + c2];
#pragma unroll
        for (int j = 0; j < 8; j++) {
            float4 zv = *(const float4*)&sZ[(r0 + j) * 128 + k4];
            a2[j][0] = fmaf(zv.x, u0.x, a2[j][0]);
            a2[j][1] = fmaf(zv.x, u0.y, a2[j][1]);
            a2[j][0] = fmaf(zv.y, u1.x, a2[j][0]);
            a2[j][1] = fmaf(zv.y, u1.y, a2[j][1]);
            a2[j][0] = fmaf(zv.z, u2.x, a2[j][0]);
            a2[j][1] = fmaf(zv.z, u2.y, a2[j][1]);
            a2[j][0] = fmaf(zv.w, u3.x, a2[j][0]);
            a2[j][1] = fmaf(zv.w, u3.y, a2[j][1]);
        }
    }
    // epilogue: g_h (+res) AND g_zs = relu(LN(h))*tc_next (or pool on last layer)
    float ng0 = __ldg(norm_g + ln_idx * HIDD + c2);
    float ng1 = __ldg(norm_g + ln_idx * HIDD + c2 + 1);
    float nb0 = __ldg(norm_b + ln_idx * HIDD + c2);
    float nb1 = __ldg(norm_b + ln_idx * HIDD + c2 + 1);
    float zscale = doPool ? 1.f : (__ldg(t + layer + 1) * LOG2E);
    float bb0 = sb2[c2], bb1 = sb2[c2 + 1];
    float lsum0 = 0.f, lsum1 = 0.f, lmax0 = 0.f, lmax1 = 0.f;
#pragma unroll
    for (int j = 0; j < 8; j++) {
        int n = nodeBase + r0 + j;
        float o0 = a2[j][0] + bb0;
        float o1 = a2[j][1] + bb1;
        float* hp = g_h + n * HIDD + c2;
        if (n < NN && addRes) {
            float2 old = *(float2*)hp;
            o0 += old.x;
            o1 += old.y;
        }
        float sum = o0 + o1;
        float sq = fmaf(o0, o0, o1 * o1);
#pragma unroll
        for (int o = 16; o; o >>= 1) {
            sum += __shfl_xor_sync(0xffffffffu, sum, o);
            sq += __shfl_xor_sync(0xffffffffu, sq, o);
        }
        if (n < NN) {
            float mu = sum * (1.f / 64.f);
            float var = sq * (1.f / 64.f) - mu * mu;
            float rs = rsqrtf(var + 1e-5f);
            float2 hw;
            hw.x = o0;
            hw.y = o1;
            *(float2*)hp = hw;
            float z0 = fmaxf(fmaf((o0 - mu) * rs, ng0, nb0), 0.f);
            float z1 = fmaxf(fmaf((o1 - mu) * rs, ng1, nb1), 0.f);
            if (doPool) {
                lsum0 += z0;
                lsum1 += z1;
                lmax0 = fmaxf(lmax0, z0);
                lmax1 = fmaxf(lmax1, z1);
            } else {
                float2 zw;
                zw.x = z0 * zscale;
                zw.y = z1 * zscale;
                *(float2*)(g_zs + n * HIDD + c2) = zw;
            }
        }
    }
    if (doPool) {
        atomicAdd(&sPS[c2], lsum0);
        atomicAdd(&sPS[c2 + 1], lsum1);
        atomicMax(&sPM[c2], __float_as_uint(lmax0));
        atomicMax(&sPM[c2 + 1], __float_as_uint(lmax1));
        __syncthreads();
        if (tid < 64) {
            atomicAdd(&g_psum[tid], sPS[tid]);
            atomicMax(&g_pmax[tid], sPM[tid]);
        }
    }
}

// ---------------- head: pair-pool to emb[64], emb @ W_lin + b_lin ----------------
__global__ void __launch_bounds__(64) k_head(const float* __restrict__ W_lin,
                                             const float* __restrict__ b_lin,
                                             float* __restrict__ out) {
    __shared__ float emb[64];
    int t = threadIdx.x;
    if (t < 32) {
        emb[t] = (g_psum[2 * t] + g_psum[2 * t + 1]) * (1.f / (2.f * (float)NN));
        emb[32 + t] = fmaxf(__uint_as_float(g_pmax[2 * t]), __uint_as_float(g_pmax[2 * t + 1]));
    }
    __syncthreads();
    float acc = __ldg(b_lin + t);
#pragma unroll 8
    for (int k = 0; k < 64; k++) acc = fmaf(emb[k], __ldg(W_lin + k * 64 + t), acc);
    out[t] = acc;
}

// ---------------- launch ----------------
extern "C" void kernel_launch(void* const* d_in, const int* in_sizes, int n_in,
                              void* d_out, int out_size) {
    const float* x = (const float*)d_in[0];
    const float* edge_attr = (const float*)d_in[1];
    const int* eidx = (const int*)d_in[2];
    const float* W_node = (const float*)d_in[3];
    const float* b_node = (const float*)d_in[4];
    const float* W_edge = (const float*)d_in[5];
    const float* b_edge = (const float*)d_in[6];
    const float* t = (const float*)d_in[7];
    const float* W1 = (const float*)d_in[8];
    const float* b1 = (const float*)d_in[9];
    const float* ln_g = (const float*)d_in[10];
    const float* ln_b = (const float*)d_in[11];
    const float* W2 = (const float*)d_in[12];
    const float* b2 = (const float*)d_in[13];
    const float* norm_g = (const float*)d_in[14];
    const float* norm_b = (const float*)d_in[15];
    const float* W_lin = (const float*)d_in[16];
    const float* b_lin = (const float*)d_in[17];
    float* out = (float*)d_out;

    const int* src = eidx;
    const int* dst = eidx + NE;

    const int MLP_SMEM = (8192 + 8192 + 8192 + 448 + 128) * 4;  // 100,608 B
    cudaFuncSetAttribute(k_mlp, cudaFuncAttributeMaxDynamicSharedMemorySize, MLP_SMEM);

    const int WARP_BLKS = (NN * 32 + 255) / 256;  // warp-per-node conv
    const int MLP_BLKS = (NN + 63) / 64;

    k_hist<<<512, 256>>>(dst);
    k_scan<<<SCAN_B, 256>>>();
    k_scatter_embed<<<SCAT_BLKS + EMB_BLKS, 256>>>(src, dst, edge_attr, x, W_node, b_node, t);

    // layer 0 (conv = launch #4, profiled)
    k_conv<<<WARP_BLKS, 256>>>(W_edge, b_edge, t, 0);
    k_mlp<<<MLP_BLKS, 256, MLP_SMEM>>>(W1, b1, ln_g, ln_b, W2, b2, norm_g, norm_b, t, 0, 0, 1, 0);
    // layer 1
    k_conv<<<WARP_BLKS, 256>>>(W_edge, b_edge, t, 1);
    k_mlp<<<MLP_BLKS, 256, MLP_SMEM>>>(W1, b1, ln_g, ln_b, W2, b2, norm_g, norm_b, t, 1, 1, 2, 0);
    // layer 2 (pool fused; final norm uses layer-0 params)
    k_conv<<<WARP_BLKS, 256>>>(W_edge, b_edge, t, 2);
    k_mlp<<<MLP_BLKS, 256, MLP_SMEM>>>(W1, b1, ln_g, ln_b, W2, b2, norm_g, norm_b, t, 2, 1, 0, 1);

    k_head<<<1, 64>>>(W_lin, b_lin, out);
}